// round 10
// baseline (speedup 1.0000x reference)
#include <cuda_runtime.h>
#include <cuda_fp16.h>
#include <cstdint>

#define NV 50000
#define HH 3
#define MM 10
#define APITCH 68            // u32 pitch (272B rows): conflict-free ldmatrix
#define TILE_B 34816         // 128 * 272 bytes per fp16 tile

// ---------------- device scratch (allocation-free rule) ----------------
__device__ uint4    g_Zch4 [(size_t)NV * 48];    // Zc (+bv) fp16 [n][384]
__device__ uint4    g_V8i4 [(size_t)NV * 24];    // Vint int8 [n][h*128+k]
__device__ uint4    g_V8n4 [(size_t)NV * 24];    // Vnh  int8
__device__ float4   g_si4  [HH * NV];            // {s, sc_lo, sc_hi, -} [h][n]
__device__ float4   g_sn4  [HH * NV];
__device__ float    g_ec   [HH * NV];            // Zc . a_c
__device__ uint32_t g_Wt   [9 * 128 * APITCH];   // pre-transposed W, fp16 pairs

// ---------------- helpers ----------------
__device__ __forceinline__ uint32_t smem_u32(const void* p) {
    uint32_t a;
    asm("{ .reg .u64 t; cvta.to.shared.u64 t, %1; cvt.u32.u64 %0, t; }" : "=r"(a) : "l"(p));
    return a;
}
__device__ __forceinline__ void mma16816(float c[4], const uint32_t a[4],
                                         uint32_t b0, uint32_t b1) {
    asm volatile(
        "mma.sync.aligned.m16n8k16.row.col.f32.f16.f16.f32 "
        "{%0,%1,%2,%3}, {%4,%5,%6,%7}, {%8,%9}, {%0,%1,%2,%3};"
        : "+f"(c[0]), "+f"(c[1]), "+f"(c[2]), "+f"(c[3])
        : "r"(a[0]), "r"(a[1]), "r"(a[2]), "r"(a[3]), "r"(b0), "r"(b1));
}
#define LDM4(r, addr) \
    asm volatile("ldmatrix.sync.aligned.m8n8.x4.shared.b16 {%0,%1,%2,%3}, [%4];" \
        : "=r"((r)[0]), "=r"((r)[1]), "=r"((r)[2]), "=r"((r)[3]) : "r"(addr))

__device__ __forceinline__ uint32_t packh2(float a, float b) {
    __half2 h = __float22half2_rn(make_float2(a, b));
    return *reinterpret_cast<uint32_t*>(&h);
}

// two bytes of 'src' (biased-128 uint8) -> packed f32x2 {q0,q1} exact, fma w/ als2
#define UNPACK2_ACC(src, sel0, sel1, als2, acc2, negmagic2) do { \
    uint32_t _lo, _hi; uint64_t _p; \
    asm("prmt.b32 %0, %1, %2, %3;" : "=r"(_lo) : "r"(src), "r"(0x4B000000u), "n"(sel0)); \
    asm("prmt.b32 %0, %1, %2, %3;" : "=r"(_hi) : "r"(src), "r"(0x4B000000u), "n"(sel1)); \
    asm("mov.b64 %0, {%1, %2};" : "=l"(_p) : "r"(_lo), "r"(_hi)); \
    asm("add.rn.f32x2 %0, %0, %1;" : "+l"(_p) : "l"(negmagic2)); \
    asm("fma.rn.f32x2 %0, %1, %2, %0;" : "+l"(acc2) : "l"(_p), "l"(als2)); \
} while (0)

#define UNPACK_V4(pv, als2, acc2, nm2) do { \
    UNPACK2_ACC((pv).x, 0x7440, 0x7441, als2, (acc2)[0], nm2); \
    UNPACK2_ACC((pv).x, 0x7442, 0x7443, als2, (acc2)[1], nm2); \
    UNPACK2_ACC((pv).y, 0x7440, 0x7441, als2, (acc2)[2], nm2); \
    UNPACK2_ACC((pv).y, 0x7442, 0x7443, als2, (acc2)[3], nm2); \
    UNPACK2_ACC((pv).z, 0x7440, 0x7441, als2, (acc2)[4], nm2); \
    UNPACK2_ACC((pv).z, 0x7442, 0x7443, als2, (acc2)[5], nm2); \
    UNPACK2_ACC((pv).w, 0x7440, 0x7441, als2, (acc2)[6], nm2); \
    UNPACK2_ACC((pv).w, 0x7442, 0x7443, als2, (acc2)[7], nm2); \
} while (0)

// =======================================================================
// Kernel 0: transpose weights to fp16 pairs. grid (9,4), smem-tiled.
// =======================================================================
__global__ void wprep_kernel(const float* __restrict__ Wvc,
                             const float* __restrict__ Wint,
                             const float* __restrict__ Wnh)
{
    __shared__ float ws[128][33];
    const int g  = blockIdx.x;
    const int n0 = blockIdx.y * 32;
    const float* W = (g < 3) ? (Wvc  + (size_t)g       * 16384)
                   : (g < 6) ? (Wint + (size_t)(g - 3) * 16384)
                             : (Wnh  + (size_t)(g - 6) * 16384);
    const int tid = threadIdx.x;
    #pragma unroll
    for (int i = 0; i < 16; i++) {
        int idx = tid + i * 256;
        int f = idx >> 5, j = idx & 31;
        ws[f][j] = W[f * 128 + n0 + j];
    }
    __syncthreads();
    #pragma unroll
    for (int i = 0; i < 8; i++) {
        int idx = tid + i * 256;
        int nl = idx >> 6, f2 = idx & 63;
        g_Wt[g * 128 * APITCH + (n0 + nl) * APITCH + f2] =
            packh2(ws[2 * f2][nl], ws[2 * f2 + 1][nl]);
    }
}

// smem offsets (bytes): A | B (single) | stage | scalars  -> 107008 B, 2 CTA/SM
#define OFF_A   0
#define OFF_B   TILE_B
#define OFF_STG (2 * TILE_B)
#define OFF_AV  (3 * TILE_B)
#define OFF_BV  (3 * TILE_B + 512)
#define OFF_SP  (3 * TILE_B + 1024)
#define SMEM1_TOTAL (3 * TILE_B + 2048)      // 106496 B

__device__ __forceinline__ void copy_tile_async(uint32_t dst, const uint32_t* src) {
    for (int i = threadIdx.x; i < 2176; i += 256)
        asm volatile("cp.async.cg.shared.global [%0], [%1], 16;"
                     :: "r"(dst + i * 16), "l"(src + i * 4) : "memory");
}

// =======================================================================
// Kernel 1: 9x (X@W) single-pass fp16 HMMA GEMM.
//   gg 0-2 (Zc): -> fp16 (+bv) table + e_center
//   gg 3-8 (V):  -> int8 table (per row-half scale, warp-local) + s-table
// =======================================================================
__global__ void __launch_bounds__(256, 2) prep_kernel(
    const float* __restrict__ X,
    const float* __restrict__ a,
    const float* __restrict__ bv)
{
    extern __shared__ char smem[];
    const uint32_t sb = smem_u32(smem);
    float* sm_av  = (float*)(smem + OFF_AV);
    float* sm_bv  = (float*)(smem + OFF_BV);
    float* s_part = (float*)(smem + OFF_SP);

    const int tid  = threadIdx.x;
    const int lane = tid & 31;
    const int wid  = tid >> 5;
    const int wr   = wid >> 1;
    const int wc   = wid & 1;
    const int g    = lane >> 2;
    const int tg   = lane & 3;
    const int row0 = blockIdx.x * 128;

    const uint32_t a_off = (uint32_t)((wr * 32 + (lane & 15)) * 272 + ((lane >> 4) << 4));
    const int t4 = lane >> 3;
    const uint32_t b_off = (uint32_t)((wc * 64 + ((t4 >> 1) << 3) + (lane & 7)) * 272
                                      + ((t4 & 1) << 4));

    // kick off B(0)
    copy_tile_async(sb + OFF_B, g_Wt);
    asm volatile("cp.async.commit_group;" ::: "memory");

    // ---- load A (X tile 128x128) as fp16 pairs ----
    uint32_t* As = (uint32_t*)(smem + OFF_A);
    #pragma unroll
    for (int i = 0; i < 16; i++) {
        int fid = tid + i * 256;
        int r = fid >> 5;
        int c = (fid & 31) << 2;
        float4 v = make_float4(0.f, 0.f, 0.f, 0.f);
        if (row0 + r < NV) v = *(const float4*)(X + (size_t)(row0 + r) * 128 + c);
        int o = r * APITCH + (c >> 1);
        As[o]     = packh2(v.x, v.y);
        As[o + 1] = packh2(v.z, v.w);
    }

    for (int gg = 0; gg < 9; gg++) {
        const int h = gg % 3;
        const bool isZc = (gg < 3);

        if (tid < 128) {
            sm_av[tid] = a[h * 256 + (isZc ? 128 : 0) + tid];
            if (isZc) sm_bv[tid] = bv[h * 128 + tid];
        }
        asm volatile("cp.async.wait_group 0;" ::: "memory");
        __syncthreads();   // (b) B(gg)+av ready; stage consumed by prior copy-out

        float acc[2][8][4];
        #pragma unroll
        for (int i = 0; i < 2; i++)
            #pragma unroll
            for (int j = 0; j < 8; j++)
                #pragma unroll
                for (int q = 0; q < 4; q++) acc[i][j][q] = 0.f;

        #pragma unroll
        for (int ks = 0; ks < 8; ks++) {
            const uint32_t kb = ks * 32;
            uint32_t a0[4], a1[4], bb[4][4];
            LDM4(a0, sb + OFF_A + a_off + kb);
            LDM4(a1, sb + OFF_A + a_off + 4352 + kb);
            #pragma unroll
            for (int jj = 0; jj < 4; jj++)
                LDM4(bb[jj], sb + OFF_B + b_off + jj * 4352 + kb);
            #pragma unroll
            for (int j = 0; j < 8; j++) {
                uint32_t b0 = bb[j >> 1][(j & 1) * 2];
                uint32_t b1 = bb[j >> 1][(j & 1) * 2 + 1];
                mma16816(acc[0][j], a0, b0, b1);
                mma16816(acc[1][j], a1, b0, b1);
            }
        }
        __syncthreads();   // (1) all MMA reads of B done

        // prefetch B(gg+1) into the (single) B buffer; overlaps epilogue
        if (gg < 8) {
            copy_tile_async(sb + OFF_B, g_Wt + (size_t)(gg + 1) * 128 * APITCH);
            asm volatile("cp.async.commit_group;" ::: "memory");
        }

        // ---- s-dot with av ----
        float sp[4] = {0.f, 0.f, 0.f, 0.f};
        #pragma unroll
        for (int i = 0; i < 2; i++)
            #pragma unroll
            for (int j = 0; j < 8; j++) {
                int col = wc * 64 + j * 8 + 2 * tg;
                float a0 = sm_av[col], a1 = sm_av[col + 1];
                sp[i * 2 + 0] += acc[i][j][0] * a0 + acc[i][j][1] * a1;
                sp[i * 2 + 1] += acc[i][j][2] * a0 + acc[i][j][3] * a1;
            }
        #pragma unroll
        for (int d = 1; d <= 2; d <<= 1)
            #pragma unroll
            for (int q = 0; q < 4; q++)
                sp[q] += __shfl_xor_sync(0xFFFFFFFFu, sp[q], d);
        if (tg == 0) {
            #pragma unroll
            for (int i = 0; i < 2; i++)
                #pragma unroll
                for (int half = 0; half < 2; half++)
                    s_part[wc * 128 + wr * 32 + i * 16 + half * 8 + g] = sp[i * 2 + half];
        }

        if (isZc) {
            // ---- fp16 (+bv) -> stage (pitch 68 u32, conflict-free) ----
            uint32_t* stgz = (uint32_t*)(smem + OFF_STG);
            #pragma unroll
            for (int i = 0; i < 2; i++)
                #pragma unroll
                for (int j = 0; j < 8; j++) {
                    int col = wc * 64 + j * 8 + 2 * tg;
                    float b0 = sm_bv[col], b1 = sm_bv[col + 1];
                    int rl0 = wr * 32 + i * 16 + g;
                    int so = wc * 32 + j * 4 + tg;
                    stgz[rl0 * 68 + so]       = packh2(acc[i][j][0] + b0, acc[i][j][1] + b1);
                    stgz[(rl0 + 8) * 68 + so] = packh2(acc[i][j][2] + b0, acc[i][j][3] + b1);
                }
            __syncthreads();   // (2)
            const uint4* sg4 = (const uint4*)(smem + OFF_STG);
            #pragma unroll
            for (int i = 0; i < 8; i++) {
                int e = tid + i * 256;
                int r = e >> 4, c = e & 15;
                if (row0 + r < NV)
                    g_Zch4[(size_t)(row0 + r) * 48 + h * 16 + c] = sg4[r * 17 + c];
            }
            if (tid < 128 && row0 + tid < NV)
                g_ec[h * NV + row0 + tid] = s_part[tid] + s_part[128 + tid];
        } else {
            // ---- int8 quant, warp-local per-(row, 64-col-half) scale ----
            float mx[2][2];   // [i][acc-half] -> rows (..+g) and (..+8+g)
            #pragma unroll
            for (int i = 0; i < 2; i++) {
                mx[i][0] = 1e-20f; mx[i][1] = 1e-20f;
                #pragma unroll
                for (int j = 0; j < 8; j++) {
                    mx[i][0] = fmaxf(mx[i][0], fmaxf(fabsf(acc[i][j][0]), fabsf(acc[i][j][1])));
                    mx[i][1] = fmaxf(mx[i][1], fmaxf(fabsf(acc[i][j][2]), fabsf(acc[i][j][3])));
                }
            }
            #pragma unroll
            for (int d = 1; d <= 2; d <<= 1)
                #pragma unroll
                for (int i = 0; i < 2; i++) {
                    mx[i][0] = fmaxf(mx[i][0], __shfl_xor_sync(0xFFFFFFFFu, mx[i][0], d));
                    mx[i][1] = fmaxf(mx[i][1], __shfl_xor_sync(0xFFFFFFFFu, mx[i][1], d));
                }

            uint8_t* stg = (uint8_t*)(smem + OFF_STG);
            float4* scdst = (gg < 6) ? g_si4 : g_sn4;
            #pragma unroll
            for (int i = 0; i < 2; i++)
                #pragma unroll
                for (int half = 0; half < 2; half++) {
                    int rl = wr * 32 + i * 16 + half * 8 + g;
                    float m = mx[i][half];
                    float inv = 127.0f / m;
                    #pragma unroll
                    for (int j = 0; j < 8; j++) {
                        int cc = wc * 64 + j * 8 + 2 * tg;
                        int q0 = __float2int_rn(acc[i][j][2 * half]     * inv) + 128;
                        int q1 = __float2int_rn(acc[i][j][2 * half + 1] * inv) + 128;
                        stg[rl * 144 + cc]     = (uint8_t)q0;
                        stg[rl * 144 + cc + 1] = (uint8_t)q1;
                    }
                    if (tg == 0 && row0 + rl < NV)
                        ((float*)&scdst[h * NV + row0 + rl])[1 + wc] = m * (1.0f / 127.0f);
                }
            __syncthreads();   // (2) stage complete

            uint4* T = (gg < 6) ? g_V8i4 : g_V8n4;
            #pragma unroll
            for (int i = 0; i < 4; i++) {
                int e = tid + i * 256;
                int r = e >> 3, q4 = e & 7;
                if (row0 + r < NV)
                    T[(size_t)(row0 + r) * 24 + h * 8 + q4] =
                        *(const uint4*)(stg + r * 144 + q4 * 16);
            }
            if (tid < 128 && row0 + tid < NV)
                ((float*)&scdst[h * NV + row0 + tid])[0] =
                    s_part[tid] + s_part[128 + tid];
        }
    }
}

// =======================================================================
// Kernel 2: 8 vertices / 192-thread block; 24 threads/vertex, LDG.128
// gathers, f32x2 packed unpack; V-gathers for m=0..3 prefetched across
// the softmax phase.
// =======================================================================
__global__ void __launch_bounds__(192) gather_kernel(
    const int*   __restrict__ nh_idx,
    const int*   __restrict__ int_idx,
    const float* __restrict__ nh_edges,
    const float* __restrict__ int_edges,
    float*       __restrict__ out)
{
    const int t  = threadIdx.x;
    const int nb = blockIdx.x * 8;

    __shared__ int      s_raw [8][2][MM];
    __shared__ uint32_t s_voff[8][2][MM];
    __shared__ float2   s_alpha[8][6][MM];   // {a*sc_lo, a*sc_hi} * 0.1

    if (t < 160) {
        int v = t / 20, r = t % 20;
        int br = r / 10, m = r % 10;
        int idx = (br ? nh_idx : int_idx)[(nb + v) * MM + m];
        s_raw[v][br][m]  = idx;
        s_voff[v][br][m] = (uint32_t)idx * 384u;
    }
    __syncthreads();

    // ---- prefetch V gathers for m=0..3 (independent of alpha) ----
    const int v = t / 24;
    const int q = t % 24;          // 16-byte slot (16 features)
    const int n = nb + v;
    const int h = q >> 3;
    const int shalf = (q & 4) ? 1 : 0;   // 0: cols 0-63, 1: cols 64-127 of head
    const char* Vi = (const char*)g_V8i4;
    const char* Vn = (const char*)g_V8n4;
    const uint32_t qoff = (uint32_t)q * 16u;

    uint4 pf_i[4], pf_n[4];
    #pragma unroll
    for (int m = 0; m < 4; m++) {
        pf_i[m] = *(const uint4*)(Vi + s_voff[v][0][m] + qoff);
        pf_n[m] = *(const uint4*)(Vn + s_voff[v][1][m] + qoff);
    }

    // ---- softmax phase (16-lane groups) ----
    #pragma unroll
    for (int rr = 0; rr < 4; rr++) {
        int gid  = (t >> 4) + rr * 12;     // 0..47 = 8v x 6grp
        int lane = t & 15;
        int vv = gid / 6, grp = gid % 6;
        int br = grp / 3, hh = grp % 3;
        int nn = nb + vv;
        float e = -1e30f;
        float4 ssc = make_float4(0.f, 0.f, 0.f, 0.f);
        if (lane < MM) {
            int idx = s_raw[vv][br][lane];
            ssc = br ? g_sn4[hh * NV + idx] : g_si4[hh * NV + idx];
            float ed = (br ? nh_edges : int_edges)[nn * MM + lane];
            e = (ssc.x + g_ec[hh * NV + nn]) * ed;
        }
        float mxv = e;
        #pragma unroll
        for (int d = 8; d >= 1; d >>= 1)
            mxv = fmaxf(mxv, __shfl_xor_sync(0xFFFFFFFFu, mxv, d, 16));
        float p = expf(e - mxv);
        float sum = p;
        #pragma unroll
        for (int d = 8; d >= 1; d >>= 1)
            sum += __shfl_xor_sync(0xFFFFFFFFu, sum, d, 16);
        if (lane < MM) {
            float as = p * (0.1f / sum);      // norm=10 folded
            s_alpha[vv][grp][lane] = make_float2(as * ssc.y, as * ssc.z);
        }
    }
    __syncthreads();

    const uint64_t negmagic2 = 0xCB000080CB000080ULL;   // {-8388736.f, x2}

    uint64_t acc2[8];
    {
        uint4 zp0 = g_Zch4[(size_t)n * 48 + 2 * q];
        uint4 zp1 = g_Zch4[(size_t)n * 48 + 2 * q + 1];
        const __half2* zh0 = (const __half2*)&zp0;
        const __half2* zh1 = (const __half2*)&zp1;
        #pragma unroll
        for (int i = 0; i < 4; i++) {
            float2 f0 = __half22float2(zh0[i]);
            float2 f1 = __half22float2(zh1[i]);
            asm("mov.b64 %0, {%1, %2};" : "=l"(acc2[i])
                : "r"(__float_as_uint(f0.x)), "r"(__float_as_uint(f0.y)));
            asm("mov.b64 %0, {%1, %2};" : "=l"(acc2[4 + i])
                : "r"(__float_as_uint(f1.x)), "r"(__float_as_uint(f1.y)));
        }
    }

    #pragma unroll
    for (int m = 0; m < 4; m++) {
        float2 a2 = s_alpha[v][h][m];
        float als = shalf ? a2.y : a2.x;
        uint64_t als2;
        asm("mov.b64 %0, {%1, %1};" : "=l"(als2) : "r"(__float_as_uint(als)));
        UNPACK_V4(pf_i[m], als2, acc2, negmagic2);
        float2 b2 = s_alpha[v][3 + h][m];
        float bls = shalf ? b2.y : b2.x;
        uint64_t bls2;
        asm("mov.b64 %0, {%1, %1};" : "=l"(bls2) : "r"(__float_as_uint(bls)));
        UNPACK_V4(pf_n[m], bls2, acc2, negmagic2);
    }
    #pragma unroll
    for (int m = 4; m < MM; m++) {
        uint4 pv = *(const uint4*)(Vi + s_voff[v][0][m] + qoff);
        float2 a2 = s_alpha[v][h][m];
        float als = shalf ? a2.y : a2.x;
        uint64_t als2;
        asm("mov.b64 %0, {%1, %1};" : "=l"(als2) : "r"(__float_as_uint(als)));
        UNPACK_V4(pv, als2, acc2, negmagic2);
        uint4 pw = *(const uint4*)(Vn + s_voff[v][1][m] + qoff);
        float2 b2 = s_alpha[v][3 + h][m];
        float bls = shalf ? b2.y : b2.x;
        uint64_t bls2;
        asm("mov.b64 %0, {%1, %1};" : "=l"(bls2) : "r"(__float_as_uint(bls)));
        UNPACK_V4(pw, bls2, acc2, negmagic2);
    }

    float4* out4 = (float4*)out;
    #pragma unroll
    for (int i = 0; i < 4; i++) {
        float4 o;
        uint32_t lo, hi;
        asm("mov.b64 {%0, %1}, %2;" : "=r"(lo), "=r"(hi) : "l"(acc2[2 * i]));
        o.x = fmaxf(__uint_as_float(lo), 0.f);
        o.y = fmaxf(__uint_as_float(hi), 0.f);
        asm("mov.b64 {%0, %1}, %2;" : "=r"(lo), "=r"(hi) : "l"(acc2[2 * i + 1]));
        o.z = fmaxf(__uint_as_float(lo), 0.f);
        o.w = fmaxf(__uint_as_float(hi), 0.f);
        out4[(size_t)n * 96 + q * 4 + i] = o;
    }
}

// -----------------------------------------------------------------------
extern "C" void kernel_launch(void* const* d_in, const int* in_sizes, int n_in,
                              void* d_out, int out_size)
{
    const float* vertices    = (const float*)d_in[0];
    const int*   nh_indices  = (const int*)  d_in[1];
    const int*   int_indices = (const int*)  d_in[2];
    const float* nh_edges    = (const float*)d_in[3];
    const float* int_edges   = (const float*)d_in[4];
    // d_in[5] = is_int: unused by the reference
    const float* Wvc         = (const float*)d_in[6];
    const float* bv          = (const float*)d_in[7];
    const float* Wvn_int     = (const float*)d_in[8];
    const float* Wvn_nh      = (const float*)d_in[9];
    const float* a           = (const float*)d_in[10];
    float* out = (float*)d_out;

    cudaFuncSetAttribute(prep_kernel, cudaFuncAttributeMaxDynamicSharedMemorySize, SMEM1_TOTAL);
    dim3 wgrid(9, 4);
    wprep_kernel<<<wgrid, 256>>>(Wvc, Wvn_int, Wvn_nh);
    prep_kernel<<<(NV + 127) / 128, 256, SMEM1_TOTAL>>>(vertices, a, bv);
    gather_kernel<<<NV / 8, 192>>>(nh_indices, int_indices, nh_edges, int_edges, out);
}

// round 11
// speedup vs baseline: 1.0452x; 1.0452x over previous
#include <cuda_runtime.h>
#include <cuda_fp16.h>
#include <cstdint>

#define NV 50000
#define HH 3
#define MM 10
#define APITCH 68            // u32 pitch (272B rows): conflict-free ldmatrix
#define TILE_B 34816         // 128 * 272 bytes per fp16 tile

// ---------------- device scratch (allocation-free rule) ----------------
__device__ uint4    g_Zch4 [(size_t)NV * 48];    // Zc (+bv) fp16 [n][384]
__device__ uint4    g_V8i4 [(size_t)NV * 24];    // Vint int8 [n][h*128+k]
__device__ uint4    g_V8n4 [(size_t)NV * 24];    // Vnh  int8
__device__ float4   g_si4  [HH * NV];            // {s, sc_lo, sc_hi, -} [h][n]
__device__ float4   g_sn4  [HH * NV];
__device__ float    g_ec   [HH * NV];            // Zc . a_c
__device__ uint32_t g_Wt   [9 * 128 * APITCH];   // pre-transposed W, fp16 pairs

// ---------------- helpers ----------------
__device__ __forceinline__ uint32_t smem_u32(const void* p) {
    uint32_t a;
    asm("{ .reg .u64 t; cvta.to.shared.u64 t, %1; cvt.u32.u64 %0, t; }" : "=r"(a) : "l"(p));
    return a;
}
__device__ __forceinline__ void mma16816(float c[4], const uint32_t a[4],
                                         uint32_t b0, uint32_t b1) {
    asm volatile(
        "mma.sync.aligned.m16n8k16.row.col.f32.f16.f16.f32 "
        "{%0,%1,%2,%3}, {%4,%5,%6,%7}, {%8,%9}, {%0,%1,%2,%3};"
        : "+f"(c[0]), "+f"(c[1]), "+f"(c[2]), "+f"(c[3])
        : "r"(a[0]), "r"(a[1]), "r"(a[2]), "r"(a[3]), "r"(b0), "r"(b1));
}
#define LDM4(r, addr) \
    asm volatile("ldmatrix.sync.aligned.m8n8.x4.shared.b16 {%0,%1,%2,%3}, [%4];" \
        : "=r"((r)[0]), "=r"((r)[1]), "=r"((r)[2]), "=r"((r)[3]) : "r"(addr))

__device__ __forceinline__ uint32_t packh2(float a, float b) {
    __half2 h = __float22half2_rn(make_float2(a, b));
    return *reinterpret_cast<uint32_t*>(&h);
}

// two bytes of 'src' (biased-128 uint8) -> packed f32x2 {q0,q1} exact, fma w/ als2
#define UNPACK2_ACC(src, sel0, sel1, als2, acc2, negmagic2) do { \
    uint32_t _lo, _hi; uint64_t _p; \
    asm("prmt.b32 %0, %1, %2, %3;" : "=r"(_lo) : "r"(src), "r"(0x4B000000u), "n"(sel0)); \
    asm("prmt.b32 %0, %1, %2, %3;" : "=r"(_hi) : "r"(src), "r"(0x4B000000u), "n"(sel1)); \
    asm("mov.b64 %0, {%1, %2};" : "=l"(_p) : "r"(_lo), "r"(_hi)); \
    asm("add.rn.f32x2 %0, %0, %1;" : "+l"(_p) : "l"(negmagic2)); \
    asm("fma.rn.f32x2 %0, %1, %2, %0;" : "+l"(acc2) : "l"(_p), "l"(als2)); \
} while (0)

#define UNPACK_V4(pv, als2, acc2, nm2) do { \
    UNPACK2_ACC((pv).x, 0x7440, 0x7441, als2, (acc2)[0], nm2); \
    UNPACK2_ACC((pv).x, 0x7442, 0x7443, als2, (acc2)[1], nm2); \
    UNPACK2_ACC((pv).y, 0x7440, 0x7441, als2, (acc2)[2], nm2); \
    UNPACK2_ACC((pv).y, 0x7442, 0x7443, als2, (acc2)[3], nm2); \
    UNPACK2_ACC((pv).z, 0x7440, 0x7441, als2, (acc2)[4], nm2); \
    UNPACK2_ACC((pv).z, 0x7442, 0x7443, als2, (acc2)[5], nm2); \
    UNPACK2_ACC((pv).w, 0x7440, 0x7441, als2, (acc2)[6], nm2); \
    UNPACK2_ACC((pv).w, 0x7442, 0x7443, als2, (acc2)[7], nm2); \
} while (0)

// =======================================================================
// Kernel 0: transpose weights to fp16 pairs. grid (9,4), smem-tiled.
// =======================================================================
__global__ void wprep_kernel(const float* __restrict__ Wvc,
                             const float* __restrict__ Wint,
                             const float* __restrict__ Wnh)
{
    __shared__ float ws[128][33];
    const int g  = blockIdx.x;
    const int n0 = blockIdx.y * 32;
    const float* W = (g < 3) ? (Wvc  + (size_t)g       * 16384)
                   : (g < 6) ? (Wint + (size_t)(g - 3) * 16384)
                             : (Wnh  + (size_t)(g - 6) * 16384);
    const int tid = threadIdx.x;
    #pragma unroll
    for (int i = 0; i < 16; i++) {
        int idx = tid + i * 256;
        int f = idx >> 5, j = idx & 31;
        ws[f][j] = W[f * 128 + n0 + j];
    }
    __syncthreads();
    #pragma unroll
    for (int i = 0; i < 8; i++) {
        int idx = tid + i * 256;
        int nl = idx >> 6, f2 = idx & 63;
        g_Wt[g * 128 * APITCH + (n0 + nl) * APITCH + f2] =
            packh2(ws[2 * f2][nl], ws[2 * f2 + 1][nl]);
    }
}

// smem offsets (bytes): A | B (single) | stage | scalars  -> 106496 B, 2 CTA/SM
#define OFF_A   0
#define OFF_B   TILE_B
#define OFF_STG (2 * TILE_B)
#define OFF_AV  (3 * TILE_B)
#define OFF_BV  (3 * TILE_B + 512)
#define OFF_SP  (3 * TILE_B + 1024)
#define SMEM1_TOTAL (3 * TILE_B + 2048)      // 106496 B

__device__ __forceinline__ void copy_tile_async(uint32_t dst, const uint32_t* src) {
    for (int i = threadIdx.x; i < 2176; i += 256)
        asm volatile("cp.async.cg.shared.global [%0], [%1], 16;"
                     :: "r"(dst + i * 16), "l"(src + i * 4) : "memory");
}

// =======================================================================
// Kernel 1: 9x (X@W) single-pass fp16 HMMA GEMM.
//   gg 0-2 (Zc): -> fp16 (+bv) table + e_center
//   gg 3-8 (V):  -> int8 table (per row-half scale, warp-local) + s-table
// =======================================================================
__global__ void __launch_bounds__(256, 2) prep_kernel(
    const float* __restrict__ X,
    const float* __restrict__ a,
    const float* __restrict__ bv)
{
    extern __shared__ char smem[];
    const uint32_t sb = smem_u32(smem);
    float* sm_av  = (float*)(smem + OFF_AV);
    float* sm_bv  = (float*)(smem + OFF_BV);
    float* s_part = (float*)(smem + OFF_SP);

    const int tid  = threadIdx.x;
    const int lane = tid & 31;
    const int wid  = tid >> 5;
    const int wr   = wid >> 1;
    const int wc   = wid & 1;
    const int g    = lane >> 2;
    const int tg   = lane & 3;
    const int row0 = blockIdx.x * 128;

    const uint32_t a_off = (uint32_t)((wr * 32 + (lane & 15)) * 272 + ((lane >> 4) << 4));
    const int t4 = lane >> 3;
    const uint32_t b_off = (uint32_t)((wc * 64 + ((t4 >> 1) << 3) + (lane & 7)) * 272
                                      + ((t4 & 1) << 4));

    // kick off B(0)
    copy_tile_async(sb + OFF_B, g_Wt);
    asm volatile("cp.async.commit_group;" ::: "memory");

    // ---- load A (X tile 128x128, streaming) as fp16 pairs ----
    uint32_t* As = (uint32_t*)(smem + OFF_A);
    #pragma unroll
    for (int i = 0; i < 16; i++) {
        int fid = tid + i * 256;
        int r = fid >> 5;
        int c = (fid & 31) << 2;
        float4 v = make_float4(0.f, 0.f, 0.f, 0.f);
        if (row0 + r < NV) v = __ldcs((const float4*)(X + (size_t)(row0 + r) * 128 + c));
        int o = r * APITCH + (c >> 1);
        As[o]     = packh2(v.x, v.y);
        As[o + 1] = packh2(v.z, v.w);
    }

    for (int gg = 0; gg < 9; gg++) {
        const int h = gg % 3;
        const bool isZc = (gg < 3);

        if (tid < 128) {
            sm_av[tid] = a[h * 256 + (isZc ? 128 : 0) + tid];
            if (isZc) sm_bv[tid] = bv[h * 128 + tid];
        }
        asm volatile("cp.async.wait_group 0;" ::: "memory");
        __syncthreads();   // (b) B(gg)+av ready; stage consumed by prior copy-out

        float acc[2][8][4];
        #pragma unroll
        for (int i = 0; i < 2; i++)
            #pragma unroll
            for (int j = 0; j < 8; j++)
                #pragma unroll
                for (int q = 0; q < 4; q++) acc[i][j][q] = 0.f;

        #pragma unroll
        for (int ks = 0; ks < 8; ks++) {
            const uint32_t kb = ks * 32;
            uint32_t a0[4], a1[4], bb[4][4];
            LDM4(a0, sb + OFF_A + a_off + kb);
            LDM4(a1, sb + OFF_A + a_off + 4352 + kb);
            #pragma unroll
            for (int jj = 0; jj < 4; jj++)
                LDM4(bb[jj], sb + OFF_B + b_off + jj * 4352 + kb);
            #pragma unroll
            for (int j = 0; j < 8; j++) {
                uint32_t b0 = bb[j >> 1][(j & 1) * 2];
                uint32_t b1 = bb[j >> 1][(j & 1) * 2 + 1];
                mma16816(acc[0][j], a0, b0, b1);
                mma16816(acc[1][j], a1, b0, b1);
            }
        }
        __syncthreads();   // (1) all MMA reads of B done

        // prefetch B(gg+1) into the (single) B buffer; overlaps epilogue
        if (gg < 8) {
            copy_tile_async(sb + OFF_B, g_Wt + (size_t)(gg + 1) * 128 * APITCH);
            asm volatile("cp.async.commit_group;" ::: "memory");
        }

        // ---- s-dot with av ----
        float sp[4] = {0.f, 0.f, 0.f, 0.f};
        #pragma unroll
        for (int i = 0; i < 2; i++)
            #pragma unroll
            for (int j = 0; j < 8; j++) {
                int col = wc * 64 + j * 8 + 2 * tg;
                float a0 = sm_av[col], a1 = sm_av[col + 1];
                sp[i * 2 + 0] += acc[i][j][0] * a0 + acc[i][j][1] * a1;
                sp[i * 2 + 1] += acc[i][j][2] * a0 + acc[i][j][3] * a1;
            }
        #pragma unroll
        for (int d = 1; d <= 2; d <<= 1)
            #pragma unroll
            for (int q = 0; q < 4; q++)
                sp[q] += __shfl_xor_sync(0xFFFFFFFFu, sp[q], d);
        if (tg == 0) {
            #pragma unroll
            for (int i = 0; i < 2; i++)
                #pragma unroll
                for (int half = 0; half < 2; half++)
                    s_part[wc * 128 + wr * 32 + i * 16 + half * 8 + g] = sp[i * 2 + half];
        }

        if (isZc) {
            // ---- fp16 (+bv) -> stage (pitch 68 u32, conflict-free) ----
            uint32_t* stgz = (uint32_t*)(smem + OFF_STG);
            #pragma unroll
            for (int i = 0; i < 2; i++)
                #pragma unroll
                for (int j = 0; j < 8; j++) {
                    int col = wc * 64 + j * 8 + 2 * tg;
                    float b0 = sm_bv[col], b1 = sm_bv[col + 1];
                    int rl0 = wr * 32 + i * 16 + g;
                    int so = wc * 32 + j * 4 + tg;
                    stgz[rl0 * 68 + so]       = packh2(acc[i][j][0] + b0, acc[i][j][1] + b1);
                    stgz[(rl0 + 8) * 68 + so] = packh2(acc[i][j][2] + b0, acc[i][j][3] + b1);
                }
            __syncthreads();   // (2)
            const uint4* sg4 = (const uint4*)(smem + OFF_STG);
            #pragma unroll
            for (int i = 0; i < 8; i++) {
                int e = tid + i * 256;
                int r = e >> 4, c = e & 15;
                if (row0 + r < NV)
                    g_Zch4[(size_t)(row0 + r) * 48 + h * 16 + c] = sg4[r * 17 + c];
            }
            if (tid < 128 && row0 + tid < NV)
                g_ec[h * NV + row0 + tid] = s_part[tid] + s_part[128 + tid];
        } else {
            // ---- int8 quant, warp-local per-(row, 64-col-half) scale ----
            float mx[2][2];
            #pragma unroll
            for (int i = 0; i < 2; i++) {
                mx[i][0] = 1e-20f; mx[i][1] = 1e-20f;
                #pragma unroll
                for (int j = 0; j < 8; j++) {
                    mx[i][0] = fmaxf(mx[i][0], fmaxf(fabsf(acc[i][j][0]), fabsf(acc[i][j][1])));
                    mx[i][1] = fmaxf(mx[i][1], fmaxf(fabsf(acc[i][j][2]), fabsf(acc[i][j][3])));
                }
            }
            #pragma unroll
            for (int d = 1; d <= 2; d <<= 1)
                #pragma unroll
                for (int i = 0; i < 2; i++) {
                    mx[i][0] = fmaxf(mx[i][0], __shfl_xor_sync(0xFFFFFFFFu, mx[i][0], d));
                    mx[i][1] = fmaxf(mx[i][1], __shfl_xor_sync(0xFFFFFFFFu, mx[i][1], d));
                }

            uint8_t* stg = (uint8_t*)(smem + OFF_STG);
            float4* scdst = (gg < 6) ? g_si4 : g_sn4;
            #pragma unroll
            for (int i = 0; i < 2; i++)
                #pragma unroll
                for (int half = 0; half < 2; half++) {
                    int rl = wr * 32 + i * 16 + half * 8 + g;
                    float m = mx[i][half];
                    float inv = 127.0f / m;
                    #pragma unroll
                    for (int j = 0; j < 8; j++) {
                        int cc = wc * 64 + j * 8 + 2 * tg;
                        int q0 = __float2int_rn(acc[i][j][2 * half]     * inv) + 128;
                        int q1 = __float2int_rn(acc[i][j][2 * half + 1] * inv) + 128;
                        stg[rl * 144 + cc]     = (uint8_t)q0;
                        stg[rl * 144 + cc + 1] = (uint8_t)q1;
                    }
                    if (tg == 0 && row0 + rl < NV)
                        ((float*)&scdst[h * NV + row0 + rl])[1 + wc] = m * (1.0f / 127.0f);
                }
            __syncthreads();   // (2) stage complete

            uint4* T = (gg < 6) ? g_V8i4 : g_V8n4;
            #pragma unroll
            for (int i = 0; i < 4; i++) {
                int e = tid + i * 256;
                int r = e >> 3, q4 = e & 7;
                if (row0 + r < NV)
                    T[(size_t)(row0 + r) * 24 + h * 8 + q4] =
                        *(const uint4*)(stg + r * 144 + q4 * 16);
            }
            if (tid < 128 && row0 + tid < NV)
                ((float*)&scdst[h * NV + row0 + tid])[0] =
                    s_part[tid] + s_part[128 + tid];
        }
    }
}

// =======================================================================
// Kernel 2: 8 vertices / 192-thread block; 24 threads/vertex, LDG.128
// gathers (L2-resident), streaming Zc loads + output stores (.cs).
// =======================================================================
__global__ void __launch_bounds__(192) gather_kernel(
    const int*   __restrict__ nh_idx,
    const int*   __restrict__ int_idx,
    const float* __restrict__ nh_edges,
    const float* __restrict__ int_edges,
    float*       __restrict__ out)
{
    const int t  = threadIdx.x;
    const int nb = blockIdx.x * 8;

    __shared__ int      s_raw [8][2][MM];
    __shared__ uint32_t s_voff[8][2][MM];
    __shared__ float2   s_alpha[8][6][MM];   // {a*sc_lo, a*sc_hi} * 0.1

    if (t < 160) {
        int v = t / 20, r = t % 20;
        int br = r / 10, m = r % 10;
        int idx = (br ? nh_idx : int_idx)[(nb + v) * MM + m];
        s_raw[v][br][m]  = idx;
        s_voff[v][br][m] = (uint32_t)idx * 384u;
    }
    __syncthreads();

    // ---- softmax phase (16-lane groups) ----
    #pragma unroll
    for (int rr = 0; rr < 4; rr++) {
        int gid  = (t >> 4) + rr * 12;     // 0..47 = 8v x 6grp
        int lane = t & 15;
        int vv = gid / 6, grp = gid % 6;
        int br = grp / 3, hh = grp % 3;
        int nn = nb + vv;
        float e = -1e30f;
        float4 ssc = make_float4(0.f, 0.f, 0.f, 0.f);
        if (lane < MM) {
            int idx = s_raw[vv][br][lane];
            ssc = br ? g_sn4[hh * NV + idx] : g_si4[hh * NV + idx];
            float ed = (br ? nh_edges : int_edges)[nn * MM + lane];
            e = (ssc.x + g_ec[hh * NV + nn]) * ed;
        }
        float mxv = e;
        #pragma unroll
        for (int d = 8; d >= 1; d >>= 1)
            mxv = fmaxf(mxv, __shfl_xor_sync(0xFFFFFFFFu, mxv, d, 16));
        float p = expf(e - mxv);
        float sum = p;
        #pragma unroll
        for (int d = 8; d >= 1; d >>= 1)
            sum += __shfl_xor_sync(0xFFFFFFFFu, sum, d, 16);
        if (lane < MM) {
            float as = p * (0.1f / sum);      // norm=10 folded
            s_alpha[vv][grp][lane] = make_float2(as * ssc.y, as * ssc.z);
        }
    }
    __syncthreads();

    const int v = t / 24;
    const int q = t % 24;          // 16-byte slot (16 features)
    const int n = nb + v;
    const int h = q >> 3;
    const int shalf = (q & 4) ? 1 : 0;   // col half within head
    const char* Vi = (const char*)g_V8i4;
    const char* Vn = (const char*)g_V8n4;
    const uint32_t qoff = (uint32_t)q * 16u;

    const uint64_t negmagic2 = 0xCB000080CB000080ULL;   // {-8388736.f, x2}

    uint64_t acc2[8];
    {
        uint4 zp0 = __ldcs(&g_Zch4[(size_t)n * 48 + 2 * q]);       // streaming
        uint4 zp1 = __ldcs(&g_Zch4[(size_t)n * 48 + 2 * q + 1]);
        const __half2* zh0 = (const __half2*)&zp0;
        const __half2* zh1 = (const __half2*)&zp1;
        #pragma unroll
        for (int i = 0; i < 4; i++) {
            float2 f0 = __half22float2(zh0[i]);
            float2 f1 = __half22float2(zh1[i]);
            asm("mov.b64 %0, {%1, %2};" : "=l"(acc2[i])
                : "r"(__float_as_uint(f0.x)), "r"(__float_as_uint(f0.y)));
            asm("mov.b64 %0, {%1, %2};" : "=l"(acc2[4 + i])
                : "r"(__float_as_uint(f1.x)), "r"(__float_as_uint(f1.y)));
        }
    }

    #pragma unroll
    for (int m = 0; m < MM; m++) {
        uint4 pv = *(const uint4*)(Vi + s_voff[v][0][m] + qoff);
        float2 a2 = s_alpha[v][h][m];
        float als = shalf ? a2.y : a2.x;
        uint64_t als2;
        asm("mov.b64 %0, {%1, %1};" : "=l"(als2) : "r"(__float_as_uint(als)));
        UNPACK_V4(pv, als2, acc2, negmagic2);
        uint4 pw = *(const uint4*)(Vn + s_voff[v][1][m] + qoff);
        float2 b2 = s_alpha[v][3 + h][m];
        float bls = shalf ? b2.y : b2.x;
        uint64_t bls2;
        asm("mov.b64 %0, {%1, %1};" : "=l"(bls2) : "r"(__float_as_uint(bls)));
        UNPACK_V4(pw, bls2, acc2, negmagic2);
    }

    float4* out4 = (float4*)out;
    #pragma unroll
    for (int i = 0; i < 4; i++) {
        float4 o;
        uint32_t lo, hi;
        asm("mov.b64 {%0, %1}, %2;" : "=r"(lo), "=r"(hi) : "l"(acc2[2 * i]));
        o.x = fmaxf(__uint_as_float(lo), 0.f);
        o.y = fmaxf(__uint_as_float(hi), 0.f);
        asm("mov.b64 {%0, %1}, %2;" : "=r"(lo), "=r"(hi) : "l"(acc2[2 * i + 1]));
        o.z = fmaxf(__uint_as_float(lo), 0.f);
        o.w = fmaxf(__uint_as_float(hi), 0.f);
        __stcs(&out4[(size_t)n * 96 + q * 4 + i], o);   // evict-first: protect V tables
    }
}

// -----------------------------------------------------------------------
extern "C" void kernel_launch(void* const* d_in, const int* in_sizes, int n_in,
                              void* d_out, int out_size)
{
    const float* vertices    = (const float*)d_in[0];
    const int*   nh_indices  = (const int*)  d_in[1];
    const int*   int_indices = (const int*)  d_in[2];
    const float* nh_edges    = (const float*)d_in[3];
    const float* int_edges   = (const float*)d_in[4];
    // d_in[5] = is_int: unused by the reference
    const float* Wvc         = (const float*)d_in[6];
    const float* bv          = (const float*)d_in[7];
    const float* Wvn_int     = (const float*)d_in[8];
    const float* Wvn_nh      = (const float*)d_in[9];
    const float* a           = (const float*)d_in[10];
    float* out = (float*)d_out;

    cudaFuncSetAttribute(prep_kernel, cudaFuncAttributeMaxDynamicSharedMemorySize, SMEM1_TOTAL);
    dim3 wgrid(9, 4);
    wprep_kernel<<<wgrid, 256>>>(Wvc, Wvn_int, Wvn_nh);
    prep_kernel<<<(NV + 127) / 128, 256, SMEM1_TOTAL>>>(vertices, a, bv);
    gather_kernel<<<NV / 8, 192>>>(nh_indices, int_indices, nh_edges, int_edges, out);
}

// round 12
// speedup vs baseline: 1.0472x; 1.0020x over previous
#include <cuda_runtime.h>
#include <cuda_fp16.h>
#include <cstdint>

#define NV 50000
#define HH 3
#define MM 10
#define APITCH 68            // u32 pitch (272B rows): conflict-free ldmatrix
#define TILE_B 34816         // 128 * 272 bytes per fp16 tile

// ---------------- device scratch (allocation-free rule) ----------------
__device__ uint4    g_Zch4 [(size_t)NV * 48];    // Zc (+bv) fp16 [n][384]
__device__ uint4    g_V8i4 [(size_t)NV * 24];    // Vint int8 [n][h*128+k]
__device__ uint4    g_V8n4 [(size_t)NV * 24];    // Vnh  int8
__device__ float4   g_si4  [NV * HH];            // {s, sc_lo, sc_hi, -} [n][h]
__device__ float4   g_sn4  [NV * HH];
__device__ float    g_ec   [HH * NV];            // Zc . a_c
__device__ uint32_t g_Wt   [9 * 128 * APITCH];   // pre-transposed W, fp16 pairs

// ---------------- helpers ----------------
__device__ __forceinline__ uint32_t smem_u32(const void* p) {
    uint32_t a;
    asm("{ .reg .u64 t; cvta.to.shared.u64 t, %1; cvt.u32.u64 %0, t; }" : "=r"(a) : "l"(p));
    return a;
}
__device__ __forceinline__ void mma16816(float c[4], const uint32_t a[4],
                                         uint32_t b0, uint32_t b1) {
    asm volatile(
        "mma.sync.aligned.m16n8k16.row.col.f32.f16.f16.f32 "
        "{%0,%1,%2,%3}, {%4,%5,%6,%7}, {%8,%9}, {%0,%1,%2,%3};"
        : "+f"(c[0]), "+f"(c[1]), "+f"(c[2]), "+f"(c[3])
        : "r"(a[0]), "r"(a[1]), "r"(a[2]), "r"(a[3]), "r"(b0), "r"(b1));
}
#define LDM4(r, addr) \
    asm volatile("ldmatrix.sync.aligned.m8n8.x4.shared.b16 {%0,%1,%2,%3}, [%4];" \
        : "=r"((r)[0]), "=r"((r)[1]), "=r"((r)[2]), "=r"((r)[3]) : "r"(addr))

__device__ __forceinline__ uint32_t packh2(float a, float b) {
    __half2 h = __float22half2_rn(make_float2(a, b));
    return *reinterpret_cast<uint32_t*>(&h);
}

// two bytes of 'src' (biased-128 uint8) -> packed f32x2 {q0,q1} exact, fma w/ als2
#define UNPACK2_ACC(src, sel0, sel1, als2, acc2, negmagic2) do { \
    uint32_t _lo, _hi; uint64_t _p; \
    asm("prmt.b32 %0, %1, %2, %3;" : "=r"(_lo) : "r"(src), "r"(0x4B000000u), "n"(sel0)); \
    asm("prmt.b32 %0, %1, %2, %3;" : "=r"(_hi) : "r"(src), "r"(0x4B000000u), "n"(sel1)); \
    asm("mov.b64 %0, {%1, %2};" : "=l"(_p) : "r"(_lo), "r"(_hi)); \
    asm("add.rn.f32x2 %0, %0, %1;" : "+l"(_p) : "l"(negmagic2)); \
    asm("fma.rn.f32x2 %0, %1, %2, %0;" : "+l"(acc2) : "l"(_p), "l"(als2)); \
} while (0)

#define UNPACK_V4(pv, als2, acc2, nm2) do { \
    UNPACK2_ACC((pv).x, 0x7440, 0x7441, als2, (acc2)[0], nm2); \
    UNPACK2_ACC((pv).x, 0x7442, 0x7443, als2, (acc2)[1], nm2); \
    UNPACK2_ACC((pv).y, 0x7440, 0x7441, als2, (acc2)[2], nm2); \
    UNPACK2_ACC((pv).y, 0x7442, 0x7443, als2, (acc2)[3], nm2); \
    UNPACK2_ACC((pv).z, 0x7440, 0x7441, als2, (acc2)[4], nm2); \
    UNPACK2_ACC((pv).z, 0x7442, 0x7443, als2, (acc2)[5], nm2); \
    UNPACK2_ACC((pv).w, 0x7440, 0x7441, als2, (acc2)[6], nm2); \
    UNPACK2_ACC((pv).w, 0x7442, 0x7443, als2, (acc2)[7], nm2); \
} while (0)

// =======================================================================
// Kernel 0: transpose weights to fp16 pairs. grid (9,4), smem-tiled.
// =======================================================================
__global__ void wprep_kernel(const float* __restrict__ Wvc,
                             const float* __restrict__ Wint,
                             const float* __restrict__ Wnh)
{
    __shared__ float ws[128][33];
    const int g  = blockIdx.x;
    const int n0 = blockIdx.y * 32;
    const float* W = (g < 3) ? (Wvc  + (size_t)g       * 16384)
                   : (g < 6) ? (Wint + (size_t)(g - 3) * 16384)
                             : (Wnh  + (size_t)(g - 6) * 16384);
    const int tid = threadIdx.x;
    #pragma unroll
    for (int i = 0; i < 16; i++) {
        int idx = tid + i * 256;
        int f = idx >> 5, j = idx & 31;
        ws[f][j] = W[f * 128 + n0 + j];
    }
    __syncthreads();
    #pragma unroll
    for (int i = 0; i < 8; i++) {
        int idx = tid + i * 256;
        int nl = idx >> 6, f2 = idx & 63;
        g_Wt[g * 128 * APITCH + (n0 + nl) * APITCH + f2] =
            packh2(ws[2 * f2][nl], ws[2 * f2 + 1][nl]);
    }
}

// smem offsets (bytes): A | B (single) | stage | scalars  -> 106496 B, 2 CTA/SM
#define OFF_A   0
#define OFF_B   TILE_B
#define OFF_STG (2 * TILE_B)
#define OFF_AV  (3 * TILE_B)
#define OFF_BV  (3 * TILE_B + 512)
#define OFF_SP  (3 * TILE_B + 1024)
#define SMEM1_TOTAL (3 * TILE_B + 2048)      // 106496 B

__device__ __forceinline__ void copy_tile_async(uint32_t dst, const uint32_t* src) {
    for (int i = threadIdx.x; i < 2176; i += 256)
        asm volatile("cp.async.cg.shared.global [%0], [%1], 16;"
                     :: "r"(dst + i * 16), "l"(src + i * 4) : "memory");
}

// =======================================================================
// Kernel 1: 9x (X@W) single-pass fp16 HMMA GEMM.
//   gg 0-2 (Zc): -> fp16 (+bv) table (.cs stores) + e_center
//   gg 3-8 (V):  -> int8 table (default policy: keep in L2) + s-table
// =======================================================================
__global__ void __launch_bounds__(256, 2) prep_kernel(
    const float* __restrict__ X,
    const float* __restrict__ a,
    const float* __restrict__ bv)
{
    extern __shared__ char smem[];
    const uint32_t sb = smem_u32(smem);
    float* sm_av  = (float*)(smem + OFF_AV);
    float* sm_bv  = (float*)(smem + OFF_BV);
    float* s_part = (float*)(smem + OFF_SP);

    const int tid  = threadIdx.x;
    const int lane = tid & 31;
    const int wid  = tid >> 5;
    const int wr   = wid >> 1;
    const int wc   = wid & 1;
    const int g    = lane >> 2;
    const int tg   = lane & 3;
    const int row0 = blockIdx.x * 128;

    const uint32_t a_off = (uint32_t)((wr * 32 + (lane & 15)) * 272 + ((lane >> 4) << 4));
    const int t4 = lane >> 3;
    const uint32_t b_off = (uint32_t)((wc * 64 + ((t4 >> 1) << 3) + (lane & 7)) * 272
                                      + ((t4 & 1) << 4));

    // kick off B(0)
    copy_tile_async(sb + OFF_B, g_Wt);
    asm volatile("cp.async.commit_group;" ::: "memory");

    // ---- load A (X tile 128x128, streaming) as fp16 pairs ----
    uint32_t* As = (uint32_t*)(smem + OFF_A);
    #pragma unroll
    for (int i = 0; i < 16; i++) {
        int fid = tid + i * 256;
        int r = fid >> 5;
        int c = (fid & 31) << 2;
        float4 v = make_float4(0.f, 0.f, 0.f, 0.f);
        if (row0 + r < NV) v = __ldcs((const float4*)(X + (size_t)(row0 + r) * 128 + c));
        int o = r * APITCH + (c >> 1);
        As[o]     = packh2(v.x, v.y);
        As[o + 1] = packh2(v.z, v.w);
    }

    for (int gg = 0; gg < 9; gg++) {
        const int h = gg % 3;
        const bool isZc = (gg < 3);

        if (tid < 128) {
            sm_av[tid] = a[h * 256 + (isZc ? 128 : 0) + tid];
            if (isZc) sm_bv[tid] = bv[h * 128 + tid];
        }
        asm volatile("cp.async.wait_group 0;" ::: "memory");
        __syncthreads();   // (b) B(gg)+av ready; stage consumed by prior copy-out

        float acc[2][8][4];
        #pragma unroll
        for (int i = 0; i < 2; i++)
            #pragma unroll
            for (int j = 0; j < 8; j++)
                #pragma unroll
                for (int q = 0; q < 4; q++) acc[i][j][q] = 0.f;

        #pragma unroll
        for (int ks = 0; ks < 8; ks++) {
            const uint32_t kb = ks * 32;
            uint32_t a0[4], a1[4], bb[4][4];
            LDM4(a0, sb + OFF_A + a_off + kb);
            LDM4(a1, sb + OFF_A + a_off + 4352 + kb);
            #pragma unroll
            for (int jj = 0; jj < 4; jj++)
                LDM4(bb[jj], sb + OFF_B + b_off + jj * 4352 + kb);
            #pragma unroll
            for (int j = 0; j < 8; j++) {
                uint32_t b0 = bb[j >> 1][(j & 1) * 2];
                uint32_t b1 = bb[j >> 1][(j & 1) * 2 + 1];
                mma16816(acc[0][j], a0, b0, b1);
                mma16816(acc[1][j], a1, b0, b1);
            }
        }
        __syncthreads();   // (1) all MMA reads of B done

        // prefetch B(gg+1) into the (single) B buffer; overlaps epilogue
        if (gg < 8) {
            copy_tile_async(sb + OFF_B, g_Wt + (size_t)(gg + 1) * 128 * APITCH);
            asm volatile("cp.async.commit_group;" ::: "memory");
        }

        // ---- s-dot with av ----
        float sp[4] = {0.f, 0.f, 0.f, 0.f};
        #pragma unroll
        for (int i = 0; i < 2; i++)
            #pragma unroll
            for (int j = 0; j < 8; j++) {
                int col = wc * 64 + j * 8 + 2 * tg;
                float a0 = sm_av[col], a1 = sm_av[col + 1];
                sp[i * 2 + 0] += acc[i][j][0] * a0 + acc[i][j][1] * a1;
                sp[i * 2 + 1] += acc[i][j][2] * a0 + acc[i][j][3] * a1;
            }
        #pragma unroll
        for (int d = 1; d <= 2; d <<= 1)
            #pragma unroll
            for (int q = 0; q < 4; q++)
                sp[q] += __shfl_xor_sync(0xFFFFFFFFu, sp[q], d);
        if (tg == 0) {
            #pragma unroll
            for (int i = 0; i < 2; i++)
                #pragma unroll
                for (int half = 0; half < 2; half++)
                    s_part[wc * 128 + wr * 32 + i * 16 + half * 8 + g] = sp[i * 2 + half];
        }

        if (isZc) {
            // ---- fp16 (+bv) -> stage (pitch 68 u32, conflict-free) ----
            uint32_t* stgz = (uint32_t*)(smem + OFF_STG);
            #pragma unroll
            for (int i = 0; i < 2; i++)
                #pragma unroll
                for (int j = 0; j < 8; j++) {
                    int col = wc * 64 + j * 8 + 2 * tg;
                    float b0 = sm_bv[col], b1 = sm_bv[col + 1];
                    int rl0 = wr * 32 + i * 16 + g;
                    int so = wc * 32 + j * 4 + tg;
                    stgz[rl0 * 68 + so]       = packh2(acc[i][j][0] + b0, acc[i][j][1] + b1);
                    stgz[(rl0 + 8) * 68 + so] = packh2(acc[i][j][2] + b0, acc[i][j][3] + b1);
                }
            __syncthreads();   // (2)
            const uint4* sg4 = (const uint4*)(smem + OFF_STG);
            #pragma unroll
            for (int i = 0; i < 8; i++) {
                int e = tid + i * 256;
                int r = e >> 4, c = e & 15;
                if (row0 + r < NV)   // evict-first: Zc is read once (streamed) later
                    __stcs(&g_Zch4[(size_t)(row0 + r) * 48 + h * 16 + c], sg4[r * 17 + c]);
            }
            if (tid < 128 && row0 + tid < NV)
                g_ec[h * NV + row0 + tid] = s_part[tid] + s_part[128 + tid];
        } else {
            // ---- int8 quant, warp-local per-(row, 64-col-half) scale ----
            float mx[2][2];
            #pragma unroll
            for (int i = 0; i < 2; i++) {
                mx[i][0] = 1e-20f; mx[i][1] = 1e-20f;
                #pragma unroll
                for (int j = 0; j < 8; j++) {
                    mx[i][0] = fmaxf(mx[i][0], fmaxf(fabsf(acc[i][j][0]), fabsf(acc[i][j][1])));
                    mx[i][1] = fmaxf(mx[i][1], fmaxf(fabsf(acc[i][j][2]), fabsf(acc[i][j][3])));
                }
            }
            #pragma unroll
            for (int d = 1; d <= 2; d <<= 1)
                #pragma unroll
                for (int i = 0; i < 2; i++) {
                    mx[i][0] = fmaxf(mx[i][0], __shfl_xor_sync(0xFFFFFFFFu, mx[i][0], d));
                    mx[i][1] = fmaxf(mx[i][1], __shfl_xor_sync(0xFFFFFFFFu, mx[i][1], d));
                }

            uint8_t* stg = (uint8_t*)(smem + OFF_STG);
            float4* scdst = (gg < 6) ? g_si4 : g_sn4;
            #pragma unroll
            for (int i = 0; i < 2; i++)
                #pragma unroll
                for (int half = 0; half < 2; half++) {
                    int rl = wr * 32 + i * 16 + half * 8 + g;
                    float m = mx[i][half];
                    float inv = 127.0f / m;
                    #pragma unroll
                    for (int j = 0; j < 8; j++) {
                        int cc = wc * 64 + j * 8 + 2 * tg;
                        int q0 = __float2int_rn(acc[i][j][2 * half]     * inv) + 128;
                        int q1 = __float2int_rn(acc[i][j][2 * half + 1] * inv) + 128;
                        stg[rl * 144 + cc]     = (uint8_t)q0;
                        stg[rl * 144 + cc + 1] = (uint8_t)q1;
                    }
                    if (tg == 0 && row0 + rl < NV)   // n-major: [n][h]
                        ((float*)&scdst[(size_t)(row0 + rl) * HH + h])[1 + wc] =
                            m * (1.0f / 127.0f);
                }
            __syncthreads();   // (2) stage complete

            uint4* T = (gg < 6) ? g_V8i4 : g_V8n4;
            #pragma unroll
            for (int i = 0; i < 4; i++) {
                int e = tid + i * 256;
                int r = e >> 3, q4 = e & 7;
                if (row0 + r < NV)
                    T[(size_t)(row0 + r) * 24 + h * 8 + q4] =
                        *(const uint4*)(stg + r * 144 + q4 * 16);
            }
            if (tid < 128 && row0 + tid < NV)
                ((float*)&scdst[(size_t)(row0 + tid) * HH + h])[0] =
                    s_part[tid] + s_part[128 + tid];
        }
    }
}

// =======================================================================
// Kernel 2: 8 vertices / 192-thread block; 24 threads/vertex, LDG.128
// gathers (L2-resident V), streaming Zc loads + output stores (.cs),
// n-major s-tables (3 heads of one idx share L2 lines).
// =======================================================================
__global__ void __launch_bounds__(192) gather_kernel(
    const int*   __restrict__ nh_idx,
    const int*   __restrict__ int_idx,
    const float* __restrict__ nh_edges,
    const float* __restrict__ int_edges,
    float*       __restrict__ out)
{
    const int t  = threadIdx.x;
    const int nb = blockIdx.x * 8;

    __shared__ int      s_raw [8][2][MM];
    __shared__ uint32_t s_voff[8][2][MM];
    __shared__ float2   s_alpha[8][6][MM];   // {a*sc_lo, a*sc_hi} * 0.1

    if (t < 160) {
        int v = t / 20, r = t % 20;
        int br = r / 10, m = r % 10;
        int idx = (br ? nh_idx : int_idx)[(nb + v) * MM + m];
        s_raw[v][br][m]  = idx;
        s_voff[v][br][m] = (uint32_t)idx * 384u;
    }
    __syncthreads();

    // ---- softmax phase (16-lane groups) ----
    #pragma unroll
    for (int rr = 0; rr < 4; rr++) {
        int gid  = (t >> 4) + rr * 12;     // 0..47 = 8v x 6grp
        int lane = t & 15;
        int vv = gid / 6, grp = gid % 6;
        int br = grp / 3, hh = grp % 3;
        int nn = nb + vv;
        float e = -1e30f;
        float4 ssc = make_float4(0.f, 0.f, 0.f, 0.f);
        if (lane < MM) {
            int idx = s_raw[vv][br][lane];
            ssc = br ? g_sn4[(size_t)idx * HH + hh] : g_si4[(size_t)idx * HH + hh];
            float ed = (br ? nh_edges : int_edges)[nn * MM + lane];
            e = (ssc.x + g_ec[hh * NV + nn]) * ed;
        }
        float mxv = e;
        #pragma unroll
        for (int d = 8; d >= 1; d >>= 1)
            mxv = fmaxf(mxv, __shfl_xor_sync(0xFFFFFFFFu, mxv, d, 16));
        float p = expf(e - mxv);
        float sum = p;
        #pragma unroll
        for (int d = 8; d >= 1; d >>= 1)
            sum += __shfl_xor_sync(0xFFFFFFFFu, sum, d, 16);
        if (lane < MM) {
            float as = p * (0.1f / sum);      // norm=10 folded
            s_alpha[vv][grp][lane] = make_float2(as * ssc.y, as * ssc.z);
        }
    }
    __syncthreads();

    const int v = t / 24;
    const int q = t % 24;          // 16-byte slot (16 features)
    const int n = nb + v;
    const int h = q >> 3;
    const int shalf = (q & 4) ? 1 : 0;   // col half within head
    const char* Vi = (const char*)g_V8i4;
    const char* Vn = (const char*)g_V8n4;
    const uint32_t qoff = (uint32_t)q * 16u;

    const uint64_t negmagic2 = 0xCB000080CB000080ULL;   // {-8388736.f, x2}

    uint64_t acc2[8];
    {
        uint4 zp0 = __ldcs(&g_Zch4[(size_t)n * 48 + 2 * q]);       // streaming
        uint4 zp1 = __ldcs(&g_Zch4[(size_t)n * 48 + 2 * q + 1]);
        const __half2* zh0 = (const __half2*)&zp0;
        const __half2* zh1 = (const __half2*)&zp1;
        #pragma unroll
        for (int i = 0; i < 4; i++) {
            float2 f0 = __half22float2(zh0[i]);
            float2 f1 = __half22float2(zh1[i]);
            asm("mov.b64 %0, {%1, %2};" : "=l"(acc2[i])
                : "r"(__float_as_uint(f0.x)), "r"(__float_as_uint(f0.y)));
            asm("mov.b64 %0, {%1, %2};" : "=l"(acc2[4 + i])
                : "r"(__float_as_uint(f1.x)), "r"(__float_as_uint(f1.y)));
        }
    }

    #pragma unroll
    for (int m = 0; m < MM; m++) {
        uint4 pv = *(const uint4*)(Vi + s_voff[v][0][m] + qoff);
        float2 a2 = s_alpha[v][h][m];
        float als = shalf ? a2.y : a2.x;
        uint64_t als2;
        asm("mov.b64 %0, {%1, %1};" : "=l"(als2) : "r"(__float_as_uint(als)));
        UNPACK_V4(pv, als2, acc2, negmagic2);
        uint4 pw = *(const uint4*)(Vn + s_voff[v][1][m] + qoff);
        float2 b2 = s_alpha[v][3 + h][m];
        float bls = shalf ? b2.y : b2.x;
        uint64_t bls2;
        asm("mov.b64 %0, {%1, %1};" : "=l"(bls2) : "r"(__float_as_uint(bls)));
        UNPACK_V4(pw, bls2, acc2, negmagic2);
    }

    float4* out4 = (float4*)out;
    #pragma unroll
    for (int i = 0; i < 4; i++) {
        float4 o;
        uint32_t lo, hi;
        asm("mov.b64 {%0, %1}, %2;" : "=r"(lo), "=r"(hi) : "l"(acc2[2 * i]));
        o.x = fmaxf(__uint_as_float(lo), 0.f);
        o.y = fmaxf(__uint_as_float(hi), 0.f);
        asm("mov.b64 {%0, %1}, %2;" : "=r"(lo), "=r"(hi) : "l"(acc2[2 * i + 1]));
        o.z = fmaxf(__uint_as_float(lo), 0.f);
        o.w = fmaxf(__uint_as_float(hi), 0.f);
        __stcs(&out4[(size_t)n * 96 + q * 4 + i], o);   // evict-first: protect V tables
    }
}

// -----------------------------------------------------------------------
extern "C" void kernel_launch(void* const* d_in, const int* in_sizes, int n_in,
                              void* d_out, int out_size)
{
    const float* vertices    = (const float*)d_in[0];
    const int*   nh_indices  = (const int*)  d_in[1];
    const int*   int_indices = (const int*)  d_in[2];
    const float* nh_edges    = (const float*)d_in[3];
    const float* int_edges   = (const float*)d_in[4];
    // d_in[5] = is_int: unused by the reference
    const float* Wvc         = (const float*)d_in[6];
    const float* bv          = (const float*)d_in[7];
    const float* Wvn_int     = (const float*)d_in[8];
    const float* Wvn_nh      = (const float*)d_in[9];
    const float* a           = (const float*)d_in[10];
    float* out = (float*)d_out;

    cudaFuncSetAttribute(prep_kernel, cudaFuncAttributeMaxDynamicSharedMemorySize, SMEM1_TOTAL);
    dim3 wgrid(9, 4);
    wprep_kernel<<<wgrid, 256>>>(Wvc, Wvn_int, Wvn_nh);
    prep_kernel<<<(NV + 127) / 128, 256, SMEM1_TOTAL>>>(vertices, a, bv);
    gather_kernel<<<NV / 8, 192>>>(nh_indices, int_indices, nh_edges, int_edges, out);
}